// round 13
// baseline (speedup 1.0000x reference)
#include <cuda_runtime.h>
#include <cuda_bf16.h>
#include <cstdint>

// ---------------- problem constants ----------------
#define B       8
#define N       4096
#define S       1024          // NPOINT
#define NS      32            // NSAMPLE
#define CIN     64
#define CMLP    128
#define COUT    256
#define BN_EPS  1e-5f
#define M_TOT   (B*S*NS)      // 262144 samples per channel for BN

#define HGEMM_BLOCKS ((B * N) / 64)      // 512
#define FUSED_BLOCKS (B + HGEMM_BLOCKS)  // 8 fps + 512 hgemm

// ---------------- f32x2 helpers ----------------
#define PACK2(d, lo, hi)   asm("mov.b64 %0, {%1,%2};" : "=l"(d) : "f"(lo), "f"(hi))
#define SPLAT2(d, v)       asm("mov.b64 %0, {%1,%1};" : "=l"(d) : "f"(v))
#define UNPACK2(lo, hi, d) asm("mov.b64 {%0,%1}, %2;" : "=f"(lo), "=f"(hi) : "l"(d))
#define ADD2(o, a, b)      asm("add.rn.f32x2 %0, %1, %2;" : "=l"(o) : "l"(a), "l"(b))
#define MUL2(o, a, b)      asm("mul.rn.f32x2 %0, %1, %2;" : "=l"(o) : "l"(a), "l"(b))
#define FMA2(acc, a, b)    asm("fma.rn.f32x2 %0, %1, %2, %0;" : "+l"(acc) : "l"(a), "l"(b))

// ---------------- device scratch (no allocs allowed) ----------------
__device__ float4 g_cent[B * S];                     // FPS centroids (new_xyz)
__device__ int    g_gidx[B * S * NS];                // ball query indices (1 MB)
__device__ float  g_Wf[CIN * COUT];                  // fused W1@Wc   (64x256)
__device__ float  g_bf[COUT];                        // fused b1@Wc + bc
__device__ float  g_H[(size_t)B * N * COUT];         // points@Wf + bf  (33.5 MB)
__device__ float  g_sum[COUT];
__device__ float  g_sumsq[COUT];

// ---------------- fused kernel: FPS (blocks 0..7) || hgemm (blocks 8..519) ----
// Both bodies are byte-identical to the round-11 passing kernels; fusing them
// into one launch guarantees co-residency (stream fork-join did NOT overlap
// under graph replay). hgemm reads g_Wf from the wfuse kernel launched before
// this one on the same stream; fps writes g_cent consumed by ballq after.
__global__ __launch_bounds__(256) void fps_hgemm_kernel(
        const float* __restrict__ xyz, const float* __restrict__ points) {
    __shared__ union {
        struct {
            float Ps[64 * CIN];          // row-major A tile (16 KB)
            float Wf[CIN * COUT];        // full fused weight (64 KB)
        } gm;
        unsigned long long key[2][8];    // fps block reduce keys
    } sm;

    if (blockIdx.x < B) {
        // ================= FPS body (round-11, bit-exact vs XLA) =================
        const int b = blockIdx.x;
        const float* X = xyz + (size_t)b * N * 3;
        const int tid = threadIdx.x;
        const int lane = tid & 31, wid = tid >> 5;

        unsigned long long px2[8], py2[8], pz2[8];
        float dm[16];
#pragma unroll
        for (int jj = 0; jj < 8; jj++) {
            int p0 = tid + (2 * jj) * 256;
            int p1 = p0 + 256;
            PACK2(px2[jj], X[p0 * 3 + 0], X[p1 * 3 + 0]);
            PACK2(py2[jj], X[p0 * 3 + 1], X[p1 * 3 + 1]);
            PACK2(pz2[jj], X[p0 * 3 + 2], X[p1 * 3 + 2]);
            dm[2 * jj] = 1e10f; dm[2 * jj + 1] = 1e10f;
        }

        int f = 0;                               // farthest index (block-uniform)
        for (int it = 0; it < S; it++) {
            const float cx = X[f * 3 + 0], cy = X[f * 3 + 1], cz = X[f * 3 + 2];
            if (tid == 0) g_cent[b * S + it] = make_float4(cx, cy, cz, 0.f);

            unsigned long long ncx2, ncy2, ncz2;
            {
                float nx = -cx, ny = -cy, nz = -cz;
                SPLAT2(ncx2, nx); SPLAT2(ncy2, ny); SPLAT2(ncz2, nz);
            }

            float bv[4];  int bix[4];
#pragma unroll
            for (int c = 0; c < 4; c++) { bv[c] = -1.f; bix[c] = 0x7fffffff; }

#pragma unroll
            for (int jj = 0; jj < 8; jj++) {
                const int c = jj >> 1;           // chain id (contiguous idx range)
                unsigned long long dx, dy, dz, q0, q1, q2, d2;
                ADD2(dx, px2[jj], ncx2); MUL2(q0, dx, dx);
                ADD2(dy, py2[jj], ncy2); MUL2(q1, dy, dy);
                ADD2(dz, pz2[jj], ncz2); MUL2(q2, dz, dz);
                ADD2(q0, q0, q1);        // (dx*dx + dy*dy)
                ADD2(d2, q0, q2);        // ... + dz*dz
                float d0, d1; UNPACK2(d0, d1, d2);
                float m0 = fminf(dm[2 * jj], d0);     dm[2 * jj] = m0;
                if (m0 > bv[c]) { bv[c] = m0; bix[c] = tid + (2 * jj) * 256; }
                float m1 = fminf(dm[2 * jj + 1], d1); dm[2 * jj + 1] = m1;
                if (m1 > bv[c]) { bv[c] = m1; bix[c] = tid + (2 * jj + 1) * 256; }
            }
            // merge tree: strict > so the lower chain (lower indices) wins ties
            float v01 = bv[1] > bv[0] ? bv[1] : bv[0];
            int   i01 = bv[1] > bv[0] ? bix[1] : bix[0];
            float v23 = bv[3] > bv[2] ? bv[3] : bv[2];
            int   i23 = bv[3] > bv[2] ? bix[3] : bix[2];
            bool  tmx = v23 > v01;
            float bvf = tmx ? v23 : v01;
            int   bif = tmx ? i23 : i01;

            // warp reduce: max value (bits), then min index among max-holders
            unsigned wv = __reduce_max_sync(0xffffffffu, __float_as_uint(bvf));
            unsigned cand = (__float_as_uint(bvf) == wv) ? (unsigned)bif : 0x7fffffffu;
            unsigned wbi = __reduce_min_sync(0xffffffffu, cand);

            if (lane == 0)
                sm.key[it & 1][wid] =
                    ((unsigned long long)wv << 32) | (unsigned long long)(0x7fffffffu - wbi);
            __syncthreads();

            const unsigned long long* sk = sm.key[it & 1];
            unsigned long long b0 = sk[0] > sk[1] ? sk[0] : sk[1];
            unsigned long long b1 = sk[2] > sk[3] ? sk[2] : sk[3];
            unsigned long long b2 = sk[4] > sk[5] ? sk[4] : sk[5];
            unsigned long long b3 = sk[6] > sk[7] ? sk[6] : sk[7];
            b0 = b0 > b1 ? b0 : b1;
            b2 = b2 > b3 ? b2 : b3;
            unsigned long long best = b0 > b2 ? b0 : b2;
            f = (int)(0x7fffffffu - (unsigned)(best & 0xffffffffu));
        }
    } else {
        // ================= hgemm body (round-11, unchanged) ======================
        const int r0 = (blockIdx.x - B) * 64;    // global row over B*N
        const int t  = threadIdx.x;
        const int ty = t >> 5;                   // warp id -> row group ty*8
        const int tx = t & 31;                   // lane -> col group tx*8

        for (int i = t; i < 64 * CIN; i += 256)
            sm.gm.Ps[i] = points[(size_t)r0 * CIN + i];
        {
            const float4* src = (const float4*)g_Wf;
            float4* dst = (float4*)sm.gm.Wf;
#pragma unroll
            for (int i = 0; i < 16; i++) dst[t + i * 256] = src[t + i * 256];
        }
        __syncthreads();

        unsigned long long acc[8][4];            // [row][colpair]
#pragma unroll
        for (int i = 0; i < 8; i++)
#pragma unroll
            for (int j = 0; j < 4; j++) acc[i][j] = 0ull;

#pragma unroll 4
        for (int k = 0; k < CIN; k++) {
            ulonglong2 wq0 = *(const ulonglong2*)(sm.gm.Wf + k * COUT + tx * 8);
            ulonglong2 wq1 = *(const ulonglong2*)(sm.gm.Wf + k * COUT + tx * 8 + 4);
            unsigned long long wp0 = wq0.x, wp1 = wq0.y, wp2 = wq1.x, wp3 = wq1.y;
#pragma unroll
            for (int ri = 0; ri < 8; ri++) {
                float av = sm.gm.Ps[(ty * 8 + ri) * CIN + k];     // broadcast
                unsigned long long a2; SPLAT2(a2, av);
                FMA2(acc[ri][0], a2, wp0); FMA2(acc[ri][1], a2, wp1);
                FMA2(acc[ri][2], a2, wp2); FMA2(acc[ri][3], a2, wp3);
            }
        }

        float bias[8];
        *(float4*)(bias)     = *(const float4*)(g_bf + tx * 8);
        *(float4*)(bias + 4) = *(const float4*)(g_bf + tx * 8 + 4);

#pragma unroll
        for (int ri = 0; ri < 8; ri++) {
            float v[8];
#pragma unroll
            for (int j = 0; j < 4; j++) {
                float lo, hi; UNPACK2(lo, hi, acc[ri][j]);
                v[2 * j] = lo + bias[2 * j]; v[2 * j + 1] = hi + bias[2 * j + 1];
            }
            float* o = g_H + ((size_t)r0 + ty * 8 + ri) * COUT + tx * 8;
            *(float4*)(o)     = *(float4*)(v);
            *(float4*)(o + 4) = *(float4*)(v + 4);
        }
    }
}

// ---------------- kernel: ball query ----------------
// 512 threads = 16 warps = 16 centroids per block; xyz tile staged in smem (SoA).
__global__ __launch_bounds__(512) void ballq_kernel(const float* __restrict__ xyz) {
    __shared__ float sx[N], sy[N], sz[N];     // 48 KB

    const float R2 = (float)(0.15 * 0.15);    // f64 product cast to f32, matching JAX
    const int tid  = threadIdx.x;
    const int w    = blockIdx.x * 16 + (tid >> 5);
    const int lane = tid & 31;
    const int b    = w >> 10;                 // 64 blocks per batch (16 | 1024)
    const float* X = xyz + (size_t)b * N * 3;

    for (int idx = tid; idx < N * 3; idx += 512) {
        float f = X[idx];
        int p = idx / 3, c = idx - p * 3;
        if (c == 0) sx[p] = f; else if (c == 1) sy[p] = f; else sz[p] = f;
    }
    __syncthreads();

    float4 cc = g_cent[w];
    int count = 0;
    int first = -1;
    int* out = g_gidx + w * NS;

    for (int c0 = 0; c0 < N; c0 += 32) {
        int p = c0 + lane;
        float dx = __fsub_rn(sx[p], cc.x);
        float dy = __fsub_rn(sy[p], cc.y);
        float dz = __fsub_rn(sz[p], cc.z);
        float d = __fadd_rn(__fadd_rn(__fmul_rn(dx, dx), __fmul_rn(dy, dy)),
                            __fmul_rn(dz, dz));
        bool ok = !(d > R2);
        unsigned m = __ballot_sync(0xffffffffu, ok);
        if (count == 0 && m) first = c0 + __ffs(m) - 1;
        int pos = count + __popc(m & ((1u << lane) - 1));
        if (ok && pos < NS) out[pos] = p;
        count += __popc(m);
        if (count >= NS) break;     // warp-uniform (count derived from ballot)
    }
    for (int i = count + lane; i < NS; i += 32) out[i] = first;
}

// ---------------- kernel: fuse weights  Wf = W1@Wc,  bf = b1@Wc + bc ----------
// blocks 0..63 -> row i of W1; block 64 -> b1 row (+bc) AND zeroes BN stats.
__global__ __launch_bounds__(256) void wfuse_kernel(const float* __restrict__ W1,
                                                    const float* __restrict__ b1,
                                                    const float* __restrict__ Wc,
                                                    const float* __restrict__ bc) {
    __shared__ float sv[CMLP];
    const int i = blockIdx.x;
    const int o = threadIdx.x;
    const float* src = (i < CIN) ? (W1 + i * CMLP) : b1;
    if (o < CMLP) sv[o] = src[o];
    __syncthreads();

    float acc = 0.f;
#pragma unroll 8
    for (int k = 0; k < CMLP; k++) acc += sv[k] * Wc[k * COUT + o];

    if (i < CIN) {
        g_Wf[i * COUT + o] = acc;
    } else {
        g_bf[o] = acc + bc[o];
        g_sum[o] = 0.f;                       // folded zero_stats
        g_sumsq[o] = 0.f;
    }
}

// ---------------- kernel: gather-max pool + BN stats ----------------
__global__ __launch_bounds__(256) void pool_kernel(float* __restrict__ out) {
    __shared__ int rows[NS];
    const int bs = blockIdx.x;
    const int t  = threadIdx.x;
    if (t < NS) rows[t] = g_gidx[bs * NS + t];
    __syncthreads();

    const float* Hb = g_H + ((size_t)(bs >> 10) * N) * COUT + t;   // channel t
    float maxv = -1e30f, sum = 0.f, sq = 0.f;
#pragma unroll 8
    for (int n = 0; n < NS; n++) {
        float v = Hb[(size_t)rows[n] * COUT];
        maxv = fmaxf(maxv, v);
        sum += v;
        sq  += v * v;
    }
    out[(size_t)bs * COUT + t] = maxv;          // raw max(h); normalized in pass 2
    atomicAdd(&g_sum[t], sum);
    atomicAdd(&g_sumsq[t], sq);
}

// ---------------- kernel: BN normalize + relu (in place on d_out) ----------------
__global__ __launch_bounds__(256) void norm_kernel(float* __restrict__ out,
                                                   const float* __restrict__ gamma,
                                                   const float* __restrict__ beta) {
    const int c = threadIdx.x;
    const size_t idx = (size_t)blockIdx.x * COUT + c;
    const float inv_m = 1.f / (float)M_TOT;
    float mean = g_sum[c] * inv_m;
    float var  = g_sumsq[c] * inv_m - mean * mean;
    float rstd = 1.f / sqrtf(var + BN_EPS);
    float h = out[idx];
    float v = (h - mean) * rstd * gamma[c] + beta[c];
    out[idx] = fmaxf(v, 0.f);
}

// ---------------- launch (single stream; overlap via fused kernel) ----------
extern "C" void kernel_launch(void* const* d_in, const int* in_sizes, int n_in,
                              void* d_out, int out_size) {
    const float* xyz    = (const float*)d_in[0];
    // d_in[1] = t  (unused by the reference)
    const float* points = (const float*)d_in[2];
    const float* W1     = (const float*)d_in[3];
    const float* b1     = (const float*)d_in[4];
    const float* Wc     = (const float*)d_in[5];
    const float* bc     = (const float*)d_in[6];
    const float* gamma  = (const float*)d_in[7];
    const float* beta   = (const float*)d_in[8];
    float* out = (float*)d_out;

    wfuse_kernel<<<CIN + 1, 256>>>(W1, b1, Wc, bc);
    fps_hgemm_kernel<<<FUSED_BLOCKS, 256>>>(xyz, points);
    ballq_kernel<<<(B * S) / 16, 512>>>(xyz);
    pool_kernel<<<B * S, 256>>>(out);
    norm_kernel<<<(B * S * COUT) / 256, 256>>>(out, gamma, beta);
}

// round 14
// speedup vs baseline: 1.2601x; 1.2601x over previous
#include <cuda_runtime.h>
#include <cuda_bf16.h>
#include <cstdint>

// ---------------- problem constants ----------------
#define B       8
#define N       4096
#define S       1024          // NPOINT
#define NS      32            // NSAMPLE
#define CIN     64
#define CMLP    128
#define COUT    256
#define BN_EPS  1e-5f
#define M_TOT   (B*S*NS)      // 262144 samples per channel for BN

// ---------------- f32x2 helpers ----------------
#define PACK2(d, lo, hi)   asm("mov.b64 %0, {%1,%2};" : "=l"(d) : "f"(lo), "f"(hi))
#define SPLAT2(d, v)       asm("mov.b64 %0, {%1,%1};" : "=l"(d) : "f"(v))
#define UNPACK2(lo, hi, d) asm("mov.b64 {%0,%1}, %2;" : "=f"(lo), "=f"(hi) : "l"(d))
#define ADD2(o, a, b)      asm("add.rn.f32x2 %0, %1, %2;" : "=l"(o) : "l"(a), "l"(b))
#define MUL2(o, a, b)      asm("mul.rn.f32x2 %0, %1, %2;" : "=l"(o) : "l"(a), "l"(b))
#define FMA2(acc, a, b)    asm("fma.rn.f32x2 %0, %1, %2, %0;" : "+l"(acc) : "l"(a), "l"(b))

// ---------------- device scratch (no allocs allowed) ----------------
__device__ float4 g_cent[B * S];                     // FPS centroids (new_xyz)
__device__ int    g_gidx[B * S * NS];                // ball query indices (1 MB)
__device__ float  g_Wf[CIN * COUT];                  // fused W1@Wc   (64x256)
__device__ float  g_bf[COUT];                        // fused b1@Wc + bc
__device__ float  g_H[(size_t)B * N * COUT];         // points@Wf + bf  (33.5 MB)
__device__ float  g_sum[COUT];
__device__ float  g_sumsq[COUT];

// ---------------- kernel: farthest point sampling ----------------
// 128 threads (4 warps), 32 points/thread as 16 f32x2 pairs. Same REDUX +
// single-barrier u64-key scheme as the passing round-11 kernel; shrinking
// 256->128 threads continues the proven axis (512->256 gave -135us): per-SMSP
// issue work is unchanged (1 warp x 2x instrs) while barrier arrivals, REDUX
// contention and the key scan (8 -> 4 keys) all halve.
// Tie-exactness: chain c = jj>>2 owns the contiguous ascending index range
// tid + [c*1024, c*1024+896]; in-chain updates ascend with strict >, the merge
// tree prefers lower chains on ties, warp REDUX takes min index among
// max-holders, and the u64 key (val<<32)|(0x7fffffff-idx) makes block u64-max
// == (max value, lowest index). Per-point value stream is bit-identical.
__global__ __launch_bounds__(128) void fps_kernel(const float* __restrict__ xyz) {
    const int b = blockIdx.x;
    const float* X = xyz + (size_t)b * N * 3;
    const int tid = threadIdx.x;
    const int lane = tid & 31, wid = tid >> 5;

    unsigned long long px2[16], py2[16], pz2[16];
    float dm[32];
#pragma unroll
    for (int jj = 0; jj < 16; jj++) {
        int p0 = tid + (2 * jj) * 128;
        int p1 = p0 + 128;
        PACK2(px2[jj], X[p0 * 3 + 0], X[p1 * 3 + 0]);
        PACK2(py2[jj], X[p0 * 3 + 1], X[p1 * 3 + 1]);
        PACK2(pz2[jj], X[p0 * 3 + 2], X[p1 * 3 + 2]);
        dm[2 * jj] = 1e10f; dm[2 * jj + 1] = 1e10f;
    }

    __shared__ unsigned long long s_key[2][4];

    int f = 0;                                   // farthest index (block-uniform)
    for (int it = 0; it < S; it++) {
        // uniform-address loads -> one L1 broadcast per component
        const float cx = X[f * 3 + 0], cy = X[f * 3 + 1], cz = X[f * 3 + 2];
        if (tid == 0) g_cent[b * S + it] = make_float4(cx, cy, cz, 0.f);

        unsigned long long ncx2, ncy2, ncz2;
        {
            float nx = -cx, ny = -cy, nz = -cz;
            SPLAT2(ncx2, nx); SPLAT2(ncy2, ny); SPLAT2(ncz2, nz);
        }

        float bv[4];  int bix[4];
#pragma unroll
        for (int c = 0; c < 4; c++) { bv[c] = -1.f; bix[c] = 0x7fffffff; }

#pragma unroll
        for (int jj = 0; jj < 16; jj++) {
            const int c = jj >> 2;               // chain id (contiguous idx range)
            unsigned long long dx, dy, dz, q0, q1, q2, d2;
            ADD2(dx, px2[jj], ncx2); MUL2(q0, dx, dx);
            ADD2(dy, py2[jj], ncy2); MUL2(q1, dy, dy);
            ADD2(dz, pz2[jj], ncz2); MUL2(q2, dz, dz);
            ADD2(q0, q0, q1);        // (dx*dx + dy*dy)
            ADD2(d2, q0, q2);        // ... + dz*dz
            float d0, d1; UNPACK2(d0, d1, d2);
            float m0 = fminf(dm[2 * jj], d0);     dm[2 * jj] = m0;
            if (m0 > bv[c]) { bv[c] = m0; bix[c] = tid + (2 * jj) * 128; }
            float m1 = fminf(dm[2 * jj + 1], d1); dm[2 * jj + 1] = m1;
            if (m1 > bv[c]) { bv[c] = m1; bix[c] = tid + (2 * jj + 1) * 128; }
        }
        // merge tree: strict > so the lower chain (lower indices) wins ties
        float v01 = bv[1] > bv[0] ? bv[1] : bv[0];
        int   i01 = bv[1] > bv[0] ? bix[1] : bix[0];
        float v23 = bv[3] > bv[2] ? bv[3] : bv[2];
        int   i23 = bv[3] > bv[2] ? bix[3] : bix[2];
        bool  tmx = v23 > v01;
        float bvf = tmx ? v23 : v01;
        int   bif = tmx ? i23 : i01;

        // warp reduce: max value (bits), then min index among holders of the max
        unsigned wv = __reduce_max_sync(0xffffffffu, __float_as_uint(bvf));
        unsigned cand = (__float_as_uint(bvf) == wv) ? (unsigned)bif : 0x7fffffffu;
        unsigned wbi = __reduce_min_sync(0xffffffffu, cand);

        if (lane == 0)
            s_key[it & 1][wid] =
                ((unsigned long long)wv << 32) | (unsigned long long)(0x7fffffffu - wbi);
        __syncthreads();

        // block reduce: every thread scans the 4 keys (broadcast reads, tree max)
        const unsigned long long* sk = s_key[it & 1];
        unsigned long long b0 = sk[0] > sk[1] ? sk[0] : sk[1];
        unsigned long long b1 = sk[2] > sk[3] ? sk[2] : sk[3];
        unsigned long long best = b0 > b1 ? b0 : b1;
        f = (int)(0x7fffffffu - (unsigned)(best & 0xffffffffu));
    }
}

// ---------------- kernel: ball query ----------------
// 512 threads = 16 warps = 16 centroids per block; xyz tile staged in smem (SoA).
__global__ __launch_bounds__(512) void ballq_kernel(const float* __restrict__ xyz) {
    __shared__ float sx[N], sy[N], sz[N];     // 48 KB

    const float R2 = (float)(0.15 * 0.15);    // f64 product cast to f32, matching JAX
    const int tid  = threadIdx.x;
    const int w    = blockIdx.x * 16 + (tid >> 5);
    const int lane = tid & 31;
    const int b    = w >> 10;                 // 64 blocks per batch (16 | 1024)
    const float* X = xyz + (size_t)b * N * 3;

    for (int idx = tid; idx < N * 3; idx += 512) {
        float f = X[idx];
        int p = idx / 3, c = idx - p * 3;
        if (c == 0) sx[p] = f; else if (c == 1) sy[p] = f; else sz[p] = f;
    }
    __syncthreads();

    float4 cc = g_cent[w];
    int count = 0;
    int first = -1;
    int* out = g_gidx + w * NS;

    for (int c0 = 0; c0 < N; c0 += 32) {
        int p = c0 + lane;
        float dx = __fsub_rn(sx[p], cc.x);
        float dy = __fsub_rn(sy[p], cc.y);
        float dz = __fsub_rn(sz[p], cc.z);
        float d = __fadd_rn(__fadd_rn(__fmul_rn(dx, dx), __fmul_rn(dy, dy)),
                            __fmul_rn(dz, dz));
        bool ok = !(d > R2);
        unsigned m = __ballot_sync(0xffffffffu, ok);
        if (count == 0 && m) first = c0 + __ffs(m) - 1;
        int pos = count + __popc(m & ((1u << lane) - 1));
        if (ok && pos < NS) out[pos] = p;
        count += __popc(m);
        if (count >= NS) break;     // warp-uniform (count derived from ballot)
    }
    for (int i = count + lane; i < NS; i += 32) out[i] = first;
}

// ---------------- kernel: fuse weights  Wf = W1@Wc,  bf = b1@Wc + bc ----------
// blocks 0..63 -> row i of W1; block 64 -> b1 row (+bc) AND zeroes BN stats.
__global__ __launch_bounds__(256) void wfuse_kernel(const float* __restrict__ W1,
                                                    const float* __restrict__ b1,
                                                    const float* __restrict__ Wc,
                                                    const float* __restrict__ bc) {
    __shared__ float sv[CMLP];
    const int i = blockIdx.x;
    const int o = threadIdx.x;
    const float* src = (i < CIN) ? (W1 + i * CMLP) : b1;
    if (o < CMLP) sv[o] = src[o];
    __syncthreads();

    float acc = 0.f;
#pragma unroll 8
    for (int k = 0; k < CMLP; k++) acc += sv[k] * Wc[k * COUT + o];

    if (i < CIN) {
        g_Wf[i * COUT + o] = acc;
    } else {
        g_bf[o] = acc + bc[o];
        g_sum[o] = 0.f;                       // folded zero_stats
        g_sumsq[o] = 0.f;
    }
}

// ---------------- kernel: H = points @ Wf + bf ----------------
// 512 blocks of 64 rows; 256 threads; per-thread 8 rows x 8 cols (f32x2 accs).
__global__ __launch_bounds__(256) void hgemm_kernel(const float* __restrict__ points) {
    __shared__ float Ps[64 * CIN];      // row-major A tile (16 KB)
    __shared__ float Wf[CIN * COUT];    // full fused weight (64 KB)

    const int r0 = blockIdx.x * 64;     // global row over B*N
    const int t  = threadIdx.x;
    const int ty = t >> 5;              // warp id -> row group ty*8 (warp-uniform)
    const int tx = t & 31;              // lane -> col group tx*8

    for (int i = t; i < 64 * CIN; i += 256)
        Ps[i] = points[(size_t)r0 * CIN + i];
    {
        const float4* src = (const float4*)g_Wf;
        float4* dst = (float4*)Wf;
#pragma unroll
        for (int i = 0; i < 16; i++) dst[t + i * 256] = src[t + i * 256];
    }
    __syncthreads();

    unsigned long long acc[8][4];       // [row][colpair]
#pragma unroll
    for (int i = 0; i < 8; i++)
#pragma unroll
        for (int j = 0; j < 4; j++) acc[i][j] = 0ull;

#pragma unroll 4
    for (int k = 0; k < CIN; k++) {
        ulonglong2 wq0 = *(const ulonglong2*)(Wf + k * COUT + tx * 8);
        ulonglong2 wq1 = *(const ulonglong2*)(Wf + k * COUT + tx * 8 + 4);
        unsigned long long wp0 = wq0.x, wp1 = wq0.y, wp2 = wq1.x, wp3 = wq1.y;
#pragma unroll
        for (int ri = 0; ri < 8; ri++) {
            float av = Ps[(ty * 8 + ri) * CIN + k];     // broadcast
            unsigned long long a2; SPLAT2(a2, av);
            FMA2(acc[ri][0], a2, wp0); FMA2(acc[ri][1], a2, wp1);
            FMA2(acc[ri][2], a2, wp2); FMA2(acc[ri][3], a2, wp3);
        }
    }

    float bias[8];
    *(float4*)(bias)     = *(const float4*)(g_bf + tx * 8);
    *(float4*)(bias + 4) = *(const float4*)(g_bf + tx * 8 + 4);

#pragma unroll
    for (int ri = 0; ri < 8; ri++) {
        float v[8];
#pragma unroll
        for (int j = 0; j < 4; j++) {
            float lo, hi; UNPACK2(lo, hi, acc[ri][j]);
            v[2 * j] = lo + bias[2 * j]; v[2 * j + 1] = hi + bias[2 * j + 1];
        }
        float* o = g_H + ((size_t)r0 + ty * 8 + ri) * COUT + tx * 8;
        *(float4*)(o)     = *(float4*)(v);
        *(float4*)(o + 4) = *(float4*)(v + 4);
    }
}

// ---------------- kernel: gather-max pool + BN stats ----------------
__global__ __launch_bounds__(256) void pool_kernel(float* __restrict__ out) {
    __shared__ int rows[NS];
    const int bs = blockIdx.x;
    const int t  = threadIdx.x;
    if (t < NS) rows[t] = g_gidx[bs * NS + t];
    __syncthreads();

    const float* Hb = g_H + ((size_t)(bs >> 10) * N) * COUT + t;   // channel t
    float maxv = -1e30f, sum = 0.f, sq = 0.f;
#pragma unroll 8
    for (int n = 0; n < NS; n++) {
        float v = Hb[(size_t)rows[n] * COUT];
        maxv = fmaxf(maxv, v);
        sum += v;
        sq  += v * v;
    }
    out[(size_t)bs * COUT + t] = maxv;          // raw max(h); normalized in pass 2
    atomicAdd(&g_sum[t], sum);
    atomicAdd(&g_sumsq[t], sq);
}

// ---------------- kernel: BN normalize + relu (in place on d_out) ----------------
__global__ __launch_bounds__(256) void norm_kernel(float* __restrict__ out,
                                                   const float* __restrict__ gamma,
                                                   const float* __restrict__ beta) {
    const int c = threadIdx.x;
    const size_t idx = (size_t)blockIdx.x * COUT + c;
    const float inv_m = 1.f / (float)M_TOT;
    float mean = g_sum[c] * inv_m;
    float var  = g_sumsq[c] * inv_m - mean * mean;
    float rstd = 1.f / sqrtf(var + BN_EPS);
    float h = out[idx];
    float v = (h - mean) * rstd * gamma[c] + beta[c];
    out[idx] = fmaxf(v, 0.f);
}

// ---------------- launch (round-11 sequential structure — best known) -------
extern "C" void kernel_launch(void* const* d_in, const int* in_sizes, int n_in,
                              void* d_out, int out_size) {
    const float* xyz    = (const float*)d_in[0];
    // d_in[1] = t  (unused by the reference)
    const float* points = (const float*)d_in[2];
    const float* W1     = (const float*)d_in[3];
    const float* b1     = (const float*)d_in[4];
    const float* Wc     = (const float*)d_in[5];
    const float* bc     = (const float*)d_in[6];
    const float* gamma  = (const float*)d_in[7];
    const float* beta   = (const float*)d_in[8];
    float* out = (float*)d_out;

    fps_kernel<<<B, 128>>>(xyz);
    ballq_kernel<<<(B * S) / 16, 512>>>(xyz);
    wfuse_kernel<<<CIN + 1, 256>>>(W1, b1, Wc, bc);
    hgemm_kernel<<<(B * N) / 64, 256>>>(points);
    pool_kernel<<<B * S, 256>>>(out);
    norm_kernel<<<(B * S * COUT) / 256, 256>>>(out, gamma, beta);
}